// round 6
// baseline (speedup 1.0000x reference)
#include <cuda_runtime.h>
#include <cuda_bf16.h>
#include <stdint.h>

#define D_DIM 3072
#define NB    4096
#define BM    128
#define BN    128
#define KC    32
#define NCHUNK (D_DIM / KC)        // 96 (single bf16 pass)
#define STAGES 3
#define PITCH  80                  // bytes per smem row (32 bf16 = 64B + 16B pad)
#define ATILE  (BM * PITCH)        // 10240 bytes
#define STAGE_BYTES (2 * ATILE)    // A + B
#define SMEM_TOTAL (STAGES * STAGE_BYTES)   // 61440
#define MARGIN 128.0f              // > 2 * rigorous |vhat - v| bound (~48)

// ---------------- scratch (no cudaMalloc allowed) ----------------
__device__ float g_x2[NB];
__device__ float g_y2[NB];
__device__ unsigned long long g_best[NB];
__device__ __nv_bfloat16 g_xb[(size_t)NB * D_DIM];
__device__ __nv_bfloat16 g_yb[(size_t)NB * D_DIM];
__device__ float g_v[(size_t)NB * NB];          // 64 MB approx v matrix

// ---------------- PTX helpers ----------------
__device__ __forceinline__ uint32_t smem_u32(const void* p) {
    uint32_t a;
    asm("{ .reg .u64 t; cvta.to.shared.u64 t, %1; cvt.u32.u64 %0, t; }" : "=r"(a) : "l"(p));
    return a;
}
__device__ __forceinline__ void cp_async16(uint32_t s, const void* g) {
    asm volatile("cp.async.cg.shared.global [%0], [%1], 16;\n" :: "r"(s), "l"(g) : "memory");
}
__device__ __forceinline__ void ldsm_x4(uint32_t& r0, uint32_t& r1, uint32_t& r2, uint32_t& r3,
                                        uint32_t addr) {
    asm volatile("ldmatrix.sync.aligned.m8n8.x4.shared.b16 {%0,%1,%2,%3}, [%4];"
                 : "=r"(r0), "=r"(r1), "=r"(r2), "=r"(r3) : "r"(addr));
}
__device__ __forceinline__ void mma16816(float* d, const uint32_t* a, const uint32_t* b) {
    asm volatile(
        "mma.sync.aligned.m16n8k16.row.col.f32.bf16.bf16.f32 "
        "{%0,%1,%2,%3}, {%4,%5,%6,%7}, {%8,%9}, {%0,%1,%2,%3};"
        : "+f"(d[0]), "+f"(d[1]), "+f"(d[2]), "+f"(d[3])
        : "r"(a[0]), "r"(a[1]), "r"(a[2]), "r"(a[3]), "r"(b[0]), "r"(b[1]));
}

// ---------------- fused fp32->bf16 conversion + row squared-norms ----------------
__global__ void convert_norms_kernel(const float* __restrict__ x, const float* __restrict__ y) {
    const int row = blockIdx.x;
    const bool isY = row >= NB;
    const int r = isY ? row - NB : row;
    const float* src = (isY ? y : x) + (size_t)r * D_DIM;
    __nv_bfloat16* dst = (isY ? g_yb : g_xb) + (size_t)r * D_DIM;

    float s = 0.f;
    #pragma unroll 3
    for (int k = threadIdx.x * 4; k < D_DIM; k += 256 * 4) {
        float4 v = *(const float4*)(src + k);
        s += v.x * v.x + v.y * v.y + v.z * v.z + v.w * v.w;
        __nv_bfloat162 p0 = __halves2bfloat162(__float2bfloat16(v.x), __float2bfloat16(v.y));
        __nv_bfloat162 p1 = __halves2bfloat162(__float2bfloat16(v.z), __float2bfloat16(v.w));
        ((__nv_bfloat162*)(dst + k))[0] = p0;
        ((__nv_bfloat162*)(dst + k))[1] = p1;
    }
    __shared__ float sm[256];
    sm[threadIdx.x] = s;
    __syncthreads();
    for (int o = 128; o > 0; o >>= 1) {
        if (threadIdx.x < o) sm[threadIdx.x] += sm[threadIdx.x + o];
        __syncthreads();
    }
    if (threadIdx.x == 0) {
        if (isY) g_y2[r] = sm[0];
        else     g_x2[r] = sm[0];
    }
}

// ---------------- passthrough copy + scratch reset ----------------
__global__ void init_out_kernel(const float* __restrict__ md, const int* __restrict__ ni,
                                float* __restrict__ out, int N) {
    int i = blockIdx.x * blockDim.x + threadIdx.x;
    if (i < N) {
        out[i]     = md[i];
        out[N + i] = (float)ni[i];
    }
    if (i < NB) g_best[i] = 0xFFFFFFFFFFFFFFFFULL;
}

// ---------------- main: mma.sync bf16 GEMM, stores v-hat + per-row approx min ----------------
__global__ __launch_bounds__(256, 2)
void gemm_min_kernel() {
    extern __shared__ char smem[];
    const uint32_t sb = smem_u32(smem);
    const int t   = threadIdx.x;
    const int l   = t & 31;
    const int wid = t >> 5;
    const int wm  = wid >> 2;          // 0..1 : m block of 64
    const int wn  = wid & 3;           // 0..3 : n block of 32
    const int bm  = blockIdx.y * BM;
    const int bn  = blockIdx.x * BN;

    const int r0  = t >> 2;
    const int c16 = t & 3;
    const uint32_t swOff0 = (uint32_t)r0 * PITCH + (uint32_t)c16 * 16;
    const uint32_t swOff1 = (uint32_t)(r0 + 64) * PITCH + (uint32_t)c16 * 16;
    const uint32_t gOff0  = (uint32_t)r0 * D_DIM + (uint32_t)c16 * 8;
    const uint32_t gOff1  = (uint32_t)(r0 + 64) * D_DIM + (uint32_t)c16 * 8;

    const __nv_bfloat16* A0 = g_xb + (size_t)bm * D_DIM;
    const __nv_bfloat16* B0 = g_yb + (size_t)bn * D_DIM;

    auto load_chunk = [&](int c) {
        const __nv_bfloat16* A = A0 + c * KC;
        const __nv_bfloat16* B = B0 + c * KC;
        uint32_t stage = sb + (uint32_t)(c % STAGES) * STAGE_BYTES;
        cp_async16(stage + swOff0,         A + gOff0);
        cp_async16(stage + swOff1,         A + gOff1);
        cp_async16(stage + ATILE + swOff0, B + gOff0);
        cp_async16(stage + ATILE + swOff1, B + gOff1);
        asm volatile("cp.async.commit_group;\n" ::: "memory");
    };

    load_chunk(0);
    load_chunk(1);

    const uint32_t aLane = (uint32_t)(wm * 64 + (l & 15)) * PITCH + (uint32_t)(l >> 4) * 16;
    const uint32_t bLane = (uint32_t)(wn * 32 + ((l >> 4) << 3) + (l & 7)) * PITCH +
                           (uint32_t)(((l >> 3) & 1) * 16) + ATILE;

    float acc[4][4][4];
    #pragma unroll
    for (int i = 0; i < 4; i++)
        #pragma unroll
        for (int j = 0; j < 4; j++)
            #pragma unroll
            for (int q = 0; q < 4; q++) acc[i][j][q] = 0.f;

    for (int c = 0; c < NCHUNK; c++) {
        if (c < NCHUNK - 1) asm volatile("cp.async.wait_group 1;\n" ::: "memory");
        else                asm volatile("cp.async.wait_group 0;\n" ::: "memory");
        __syncthreads();
        if (c <= NCHUNK - 3) load_chunk(c + 2);

        const uint32_t stage = sb + (uint32_t)(c % STAGES) * STAGE_BYTES;
        #pragma unroll
        for (int ks = 0; ks < 2; ks++) {
            uint32_t a[4][4], b[2][4];
            #pragma unroll
            for (int i = 0; i < 4; i++)
                ldsm_x4(a[i][0], a[i][1], a[i][2], a[i][3],
                        stage + aLane + (uint32_t)i * 16 * PITCH + (uint32_t)ks * 32);
            #pragma unroll
            for (int jp = 0; jp < 2; jp++)
                ldsm_x4(b[jp][0], b[jp][1], b[jp][2], b[jp][3],
                        stage + bLane + (uint32_t)jp * 16 * PITCH + (uint32_t)ks * 32);
            #pragma unroll
            for (int i = 0; i < 4; i++) {
                #pragma unroll
                for (int jp = 0; jp < 2; jp++) {
                    mma16816(acc[i][jp * 2 + 0], a[i], &b[jp][0]);
                    mma16816(acc[i][jp * 2 + 1], a[i], &b[jp][2]);
                }
            }
        }
    }
    __syncthreads();

    float* y2s = (float*)smem;
    if (t < BN) y2s[t] = g_y2[bn + t];
    __syncthreads();

    // epilogue: v-hat = y2[n] - 2*dot; store matrix + per-row approx min
    const int nbase = wn * 32 + 2 * (l & 3);
    #pragma unroll
    for (int i = 0; i < 4; i++) {
        const int rA = bm + wm * 64 + i * 16 + (l >> 2);
        const int rB = rA + 8;
        float vA = 3.4e38f, vB = 3.4e38f;
        int   jA = 0,       jB = 0;
        #pragma unroll
        for (int j = 0; j < 4; j++) {
            int n0 = nbase + j * 8;
            float y20 = y2s[n0], y21 = y2s[n0 + 1];
            float v0 = fmaf(-2.f, acc[i][j][0], y20);
            float v1 = fmaf(-2.f, acc[i][j][1], y21);
            float v2 = fmaf(-2.f, acc[i][j][2], y20);
            float v3 = fmaf(-2.f, acc[i][j][3], y21);
            *(float2*)&g_v[(size_t)rA * NB + bn + n0] = make_float2(v0, v1);
            *(float2*)&g_v[(size_t)rB * NB + bn + n0] = make_float2(v2, v3);
            if (v0 < vA) { vA = v0; jA = n0; }
            if (v1 < vA) { vA = v1; jA = n0 + 1; }
            if (v2 < vB) { vB = v2; jB = n0; }
            if (v3 < vB) { vB = v3; jB = n0 + 1; }
        }
        unsigned long long keyA =
            ((unsigned long long)__float_as_uint(vA) << 32) | (unsigned)(bn + jA);
        unsigned long long keyB =
            ((unsigned long long)__float_as_uint(vB) << 32) | (unsigned)(bn + jB);
        #pragma unroll
        for (int o = 1; o < 4; o <<= 1) {
            unsigned long long oA = __shfl_xor_sync(0xffffffffu, keyA, o);
            unsigned long long oB = __shfl_xor_sync(0xffffffffu, keyB, o);
            if (oA < keyA) keyA = oA;
            if (oB < keyB) keyB = oB;
        }
        if ((l & 3) == 0) {
            atomicMin(&g_best[rA], keyA);
            atomicMin(&g_best[rB], keyB);
        }
    }
}

// ---------------- refine: rigorous candidate recheck + finalize ----------------
__global__ __launch_bounds__(256)
void refine_kernel(const float* __restrict__ x, const float* __restrict__ y,
                   const float* __restrict__ md, float* __restrict__ out,
                   int N, const int* __restrict__ xs, const int* __restrict__ ys) {
    const int row = blockIdx.x;
    __shared__ int s_cnt;
    __shared__ int s_cand[128];
    __shared__ unsigned long long s_best;
    if (threadIdx.x == 0) { s_cnt = 0; s_best = 0xFFFFFFFFFFFFFFFFULL; }
    __syncthreads();

    const float vhatmin = __uint_as_float((unsigned)(g_best[row] >> 32));
    const float thresh  = vhatmin + MARGIN;
    const float* vrow = g_v + (size_t)row * NB;
    for (int j = threadIdx.x; j < NB; j += 256) {
        if (vrow[j] <= thresh) {
            int p = atomicAdd(&s_cnt, 1);
            if (p < 128) s_cand[p] = j;
        }
    }
    __syncthreads();
    const int nc = min(s_cnt, 128);
    const int wid = threadIdx.x >> 5;
    const int l   = threadIdx.x & 31;
    const float* xr = x + (size_t)row * D_DIM;

    for (int c = wid; c < nc; c += 8) {
        const int j = s_cand[c];
        const float* yr = y + (size_t)j * D_DIM;
        double s = 0.0;
        #pragma unroll 4
        for (int k = l * 4; k < D_DIM; k += 32 * 4) {
            float4 xv = *(const float4*)(xr + k);
            float4 yv = *(const float4*)(yr + k);
            s += (double)xv.x * yv.x + (double)xv.y * yv.y +
                 (double)xv.z * yv.z + (double)xv.w * yv.w;
        }
        #pragma unroll
        for (int o = 16; o > 0; o >>= 1) s += __shfl_xor_sync(0xffffffffu, s, o);
        if (l == 0) {
            float v = (float)((double)g_y2[j] - 2.0 * s);
            unsigned long long key =
                ((unsigned long long)__float_as_uint(v) << 32) | (unsigned)j;
            atomicMin(&s_best, key);
        }
    }
    __syncthreads();
    if (threadIdx.x == 0) {
        unsigned long long key = s_best;
        float v = __uint_as_float((unsigned)(key >> 32));
        int   j = (int)(unsigned)(key & 0xffffffffULL);
        float dist = sqrtf(fmaxf(g_x2[row] + v, 0.f));
        const int x0 = xs[0];
        const int y0 = ys[0];
        out[x0 + row]     = fminf(dist, md[x0 + row]);
        out[N + x0 + row] = (float)(j + y0);
    }
}

// ---------------- launch ----------------
extern "C" void kernel_launch(void* const* d_in, const int* in_sizes, int n_in,
                              void* d_out, int out_size) {
    const float* x  = (const float*)d_in[0];
    const float* y  = (const float*)d_in[1];
    const float* md = (const float*)d_in[2];
    const int*   ni = (const int*)d_in[3];
    const int*   xs = (const int*)d_in[4];
    const int*   ys = (const int*)d_in[5];
    float* out = (float*)d_out;
    const int N = in_sizes[2];   // 50000

    cudaFuncSetAttribute(gemm_min_kernel,
                         cudaFuncAttributeMaxDynamicSharedMemorySize, SMEM_TOTAL);

    convert_norms_kernel<<<2 * NB, 256>>>(x, y);
    init_out_kernel<<<(N + 255) / 256, 256>>>(md, ni, out, N);
    dim3 grid(NB / BN, NB / BM);
    gemm_min_kernel<<<grid, 256, SMEM_TOTAL>>>();
    refine_kernel<<<NB, 256>>>(x, y, md, out, N, xs, ys);
}